// round 2
// baseline (speedup 1.0000x reference)
#include <cuda_runtime.h>
#include <cub/cub.cuh>

// Defeat --use_fast_math's expf -> __expf macro substitution so we call the
// accurate libdevice __nv_expf, matching XLA's f32 exp bit-for-bit.
#ifdef expf
#undef expf
#endif

#define NB      4        // batch
#define NP      34125    // priors
#define NSEL    5000     // NMS_TOP_K
#define TOPK    750
#define NW      79       // ceil(NSEL/64)
#define CONF_T  0.05f
#define NMS_T   0.3f

// ---------------- static device scratch (no allocations allowed) ------------
__device__ unsigned int g_keys_in [NB * NP];
__device__ unsigned int g_vals_in [NB * NP];
__device__ unsigned int g_keys_out[NB * NP];
__device__ unsigned int g_vals_out[NB * NP];
__device__ int          g_offs[NB + 1] = {0, NP, 2 * NP, 3 * NP, 4 * NP};

__device__ float g_bx1[NB * NSEL];
__device__ float g_by1[NB * NSEL];
__device__ float g_bx2[NB * NSEL];
__device__ float g_by2[NB * NSEL];
__device__ float g_sc [NB * NSEL];

__device__ unsigned long long g_mask[(size_t)NB * NSEL * NW]; // ~12.6 MB
__device__ unsigned char      g_temp[1u << 24];               // cub temp, 16 MB

// ---------------- kernels ---------------------------------------------------

__device__ __forceinline__ unsigned int f2sortable(float f) {
    unsigned int b = __float_as_uint(f);
    return (b & 0x80000000u) ? ~b : (b | 0x80000000u);
}
__device__ __forceinline__ float sortable2f(unsigned int u) {
    return __uint_as_float((u & 0x80000000u) ? (u & 0x7fffffffu) : ~u);
}

__global__ void k_build(const float* __restrict__ conf) {
    int i = blockIdx.x * blockDim.x + threadIdx.x;
    if (i >= NB * NP) return;
    float c = conf[2 * i + 1];                 // class-1 score
    float s = (c > CONF_T) ? c : -1e30f;
    g_keys_in[i] = f2sortable(s);
    g_vals_in[i] = (unsigned int)(i % NP);
}

__global__ void k_gather(const float* __restrict__ loc,
                         const float* __restrict__ prior) {
    int t = blockIdx.x * blockDim.x + threadIdx.x;
    if (t >= NB * NSEL) return;
    int img = t / NSEL, j = t % NSEL;
    unsigned int u = g_keys_out[img * NP + j];
    unsigned int p = g_vals_out[img * NP + j];
    g_sc[t] = sortable2f(u);

    const float* l  = loc   + ((size_t)img * NP + p) * 4;
    const float* pr = prior + (size_t)p * 4;
    float lx = l[0],  ly = l[1],  lw = l[2],  lh = l[3];
    float px = pr[0], py = pr[1], pw = pr[2], ph = pr[3];

    // xy = p_xy + (l_xy * 0.1) * p_wh ; wh = p_wh * exp(l_wh * 0.2)
    float cx = __fadd_rn(px, __fmul_rn(__fmul_rn(lx, 0.1f), pw));
    float cy = __fadd_rn(py, __fmul_rn(__fmul_rn(ly, 0.1f), ph));
    float w  = __fmul_rn(pw, expf(__fmul_rn(lw, 0.2f)));
    float h  = __fmul_rn(ph, expf(__fmul_rn(lh, 0.2f)));
    float x1 = __fsub_rn(cx, __fmul_rn(w, 0.5f));
    float y1 = __fsub_rn(cy, __fmul_rn(h, 0.5f));
    float x2 = __fadd_rn(x1, w);
    float y2 = __fadd_rn(y1, h);
    g_bx1[t] = x1; g_by1[t] = y1; g_bx2[t] = x2; g_by2[t] = y2;
}

// Upper-triangular tiled IoU bitmask. block = 64 threads (one row each),
// blockIdx.x = col tile, blockIdx.y = row tile, blockIdx.z = image.
__global__ void k_mask() {
    int bx = blockIdx.x, by = blockIdx.y, img = blockIdx.z;
    if (bx < by) return;   // only words w >= i>>6 are ever read downstream
    __shared__ float sx1[64], sy1[64], sx2[64], sy2[64], sa[64];
    int t  = threadIdx.x;
    int j0 = bx * 64;
    int jj = j0 + t;
    if (jj < NSEL) {
        int o = img * NSEL + jj;
        float x1 = g_bx1[o], y1 = g_by1[o], x2 = g_bx2[o], y2 = g_by2[o];
        sx1[t] = x1; sy1[t] = y1; sx2[t] = x2; sy2[t] = y2;
        sa[t] = __fmul_rn(__fsub_rn(x2, x1), __fsub_rn(y2, y1));
    }
    __syncthreads();
    int i = by * 64 + t;
    if (i >= NSEL) return;
    int oi = img * NSEL + i;
    float ix1 = g_bx1[oi], iy1 = g_by1[oi], ix2 = g_bx2[oi], iy2 = g_by2[oi];
    float ia  = __fmul_rn(__fsub_rn(ix2, ix1), __fsub_rn(iy2, iy1));
    int cnt = min(64, NSEL - j0);
    unsigned long long bits = 0ull;
#pragma unroll 4
    for (int c = 0; c < cnt; c++) {
        int j = j0 + c;
        if (j <= i) continue;
        float iw = fmaxf(__fsub_rn(fminf(ix2, sx2[c]), fmaxf(ix1, sx1[c])), 0.0f);
        float ih = fmaxf(__fsub_rn(fminf(iy2, sy2[c]), fmaxf(iy1, sy1[c])), 0.0f);
        float inter = __fmul_rn(iw, ih);
        float den   = __fsub_rn(__fadd_rn(ia, sa[c]), inter);
        float iou   = __fdiv_rn(inter, den);
        if (iou > NMS_T) bits |= (1ull << c);
    }
    g_mask[((size_t)img * NSEL + i) * NW + bx] = bits;
}

__global__ void k_zero(float* __restrict__ out, int n) {
    int i = blockIdx.x * blockDim.x + threadIdx.x;
    if (i < n) out[i] = 0.0f;
}

// One warp per image: greedy sequential reduce over the precomputed bitmasks.
// remv words distributed 3-per-lane in registers. Early exit at 750 kept
// (reference drops rank >= TOPK via scatter mode='drop').
__global__ void k_seq(float* __restrict__ out) {
    int img = blockIdx.x;
    __shared__ float ssc[NSEL];
    for (int i = threadIdx.x; i < NSEL; i += blockDim.x)
        ssc[i] = g_sc[img * NSEL + i];
    __syncthreads();
    if (threadIdx.x >= 32) return;
    int lane = threadIdx.x;
    unsigned long long r0 = 0, r1 = 0, r2 = 0;
    int rank = 0;
    const unsigned long long* mbase = g_mask + (size_t)img * NSEL * NW;
    for (int i = 0; i < NSEL; i++) {
        int w = i >> 6;
        int slot = w >> 5;
        unsigned long long myw = (slot == 0) ? r0 : ((slot == 1) ? r1 : r2);
        unsigned long long rw = __shfl_sync(0xffffffffu, myw, w & 31);
        bool sup = (rw >> (i & 63)) & 1ull;
        float sc = ssc[i];
        if (!sup && sc > CONF_T) {
            if (lane == 0) {
                int o = img * NSEL + i;
                float* row = out + ((size_t)(img * 2 + 1) * TOPK + rank) * 5;
                row[0] = sc;
                row[1] = g_bx1[o]; row[2] = g_by1[o];
                row[3] = g_bx2[o]; row[4] = g_by2[o];
            }
            rank++;
            if (rank >= TOPK) break;
            const unsigned long long* mr = mbase + (size_t)i * NW;
            int w0 = lane;
            int w1 = lane + 32;
            int w2 = lane + 64;
            if (w0 >= w)            r0 |= mr[w0];
            if (w1 >= w)            r1 |= mr[w1];
            if (w2 >= w && w2 < NW) r2 |= mr[w2];
        }
    }
}

// ---------------- launch ----------------------------------------------------

extern "C" void kernel_launch(void* const* d_in, const int* in_sizes, int n_in,
                              void* d_out, int out_size) {
    const float* loc   = (const float*)d_in[0];
    const float* conf  = (const float*)d_in[1];
    const float* prior = (const float*)d_in[2];
    float* out = (float*)d_out;

    void *keys_in_p, *vals_in_p, *keys_out_p, *vals_out_p, *offs_p, *temp_p;
    cudaGetSymbolAddress(&keys_in_p,  g_keys_in);
    cudaGetSymbolAddress(&vals_in_p,  g_vals_in);
    cudaGetSymbolAddress(&keys_out_p, g_keys_out);
    cudaGetSymbolAddress(&vals_out_p, g_vals_out);
    cudaGetSymbolAddress(&offs_p,     g_offs);
    cudaGetSymbolAddress(&temp_p,     g_temp);

    k_build<<<(NB * NP + 255) / 256, 256>>>(conf);

    size_t tmp_bytes = 0;
    cub::DeviceSegmentedRadixSort::SortPairsDescending(
        nullptr, tmp_bytes,
        (const unsigned int*)keys_in_p,  (unsigned int*)keys_out_p,
        (const unsigned int*)vals_in_p,  (unsigned int*)vals_out_p,
        NB * NP, NB,
        (const int*)offs_p, ((const int*)offs_p) + 1,
        0, 32, (cudaStream_t)0);
    if (tmp_bytes > (size_t)(1u << 24)) tmp_bytes = (size_t)(1u << 24);
    cub::DeviceSegmentedRadixSort::SortPairsDescending(
        temp_p, tmp_bytes,
        (const unsigned int*)keys_in_p,  (unsigned int*)keys_out_p,
        (const unsigned int*)vals_in_p,  (unsigned int*)vals_out_p,
        NB * NP, NB,
        (const int*)offs_p, ((const int*)offs_p) + 1,
        0, 32, (cudaStream_t)0);

    k_gather<<<(NB * NSEL + 255) / 256, 256>>>(loc, prior);

    dim3 mg(NW, NW, NB);
    k_mask<<<mg, 64>>>();

    k_zero<<<(out_size + 255) / 256, 256>>>(out, out_size);
    k_seq<<<NB, 256>>>(out);
}